// round 15
// baseline (speedup 1.0000x reference)
#include <cuda_runtime.h>
#include <cuda_fp16.h>

#define BB 8
#define CC 64
#define NP 16384
#define RR 32
#define NV 32768          // 32^3
#define ALPHA 0.1f
#define BNEPS 1e-4f
#define VOXEPS 1e-6f

// ---------------- scratch (device globals; no allocation allowed) ----------
__device__ float g_fT[BB * NP * CC];        // features transposed [b][n][c]
__device__ float g_tmp[BB * NV * CC];       // voxel sums [b][v][c]; later raw conv2 out
__device__ float g_cnt[BB * NV];            // voxel counts
__device__ float g_bufB[BB * CC * NV];      // conv1 output (channels-last [b][v][c])
__device__ float g_pT[BB * NP * CC];        // point branch [b][n][c]
__device__ float g_normc[BB * 3 * NP];      // normalized coords in [0,31]
__device__ float g_cmean[BB * 3];           // coordinate SUMS
__device__ unsigned g_cmaxb[BB];            // max dist^2 as float bits
__device__ float g_stats[6 * CC];           // sum1,sq1,sum2,sq2,psum,psq
__device__ float g_scsh[6 * CC];            // sc1,sh1,sc2,sh2,scp,shp

// ---------------- utility kernels ----------------
// zero tmp + cnt + stats + cmean + cmaxb in ONE launch
__global__ void zero_all(float* tmp, float* cnt, float* stats, float* cmean,
                         unsigned* cmaxb) {
    size_t i = (size_t)blockIdx.x * blockDim.x + threadIdx.x;
    size_t stride = (size_t)gridDim.x * blockDim.x;
    const size_t ntmp = (size_t)BB * NV * CC;
    for (size_t k = i; k < ntmp; k += stride) tmp[k] = 0.0f;
    for (size_t k = i; k < (size_t)BB * NV; k += stride) cnt[k] = 0.0f;
    if (i < 6 * CC) stats[i] = 0.0f;
    if (i < BB * 3) cmean[i] = 0.0f;
    if (i < BB) cmaxb[i] = 0u;
}

__global__ void copy_kernel(const float* __restrict__ src, float* __restrict__ dst, int n) {
    int i = blockIdx.x * blockDim.x + threadIdx.x;
    int stride = gridDim.x * blockDim.x;
    for (; i < n; i += stride) dst[i] = src[i];
}

__global__ void mkscale(const float* __restrict__ sum, const float* __restrict__ sumsq,
                        const float* __restrict__ gamma, const float* __restrict__ beta,
                        float invcnt, float* __restrict__ sc, float* __restrict__ sh) {
    int c = threadIdx.x;
    float mean = sum[c] * invcnt;
    float var = sumsq[c] * invcnt - mean * mean;
    float s = gamma[c] * rsqrtf(var + BNEPS);
    sc[c] = s;
    sh[c] = beta[c] - mean * s;
}

// ---------------- features transpose [b][c][n] -> [b][n][c] ----------------
__global__ void transpose_feat(const float* __restrict__ feat, float* __restrict__ fT) {
    __shared__ float s[CC][33];
    int b = blockIdx.y;
    int n0 = blockIdx.x * 32;
    int t = threadIdx.x;
    for (int i = t; i < 32 * 64; i += 256) {
        int c = i >> 5, n = i & 31;
        s[c][n] = feat[(b * CC + c) * NP + n0 + n];
    }
    __syncthreads();
    for (int i = t; i < 32 * 64; i += 256) {
        int n = i >> 6, c = i & 63;
        fT[((size_t)b * NP + n0 + n) * CC + c] = s[c][n];
    }
}

// ---------------- coord statistics ----------------
__global__ void coord_mean_p(const float* __restrict__ coords, float* __restrict__ cmean) {
    int b = blockIdx.y;
    int n0 = blockIdx.x * 512;
    int t = threadIdx.x;
    float s0 = 0, s1 = 0, s2 = 0;
    for (int n = n0 + t; n < n0 + 512; n += 256) {
        s0 += coords[(b * 3 + 0) * NP + n];
        s1 += coords[(b * 3 + 1) * NP + n];
        s2 += coords[(b * 3 + 2) * NP + n];
    }
#pragma unroll
    for (int o = 16; o > 0; o >>= 1) {
        s0 += __shfl_xor_sync(0xffffffff, s0, o);
        s1 += __shfl_xor_sync(0xffffffff, s1, o);
        s2 += __shfl_xor_sync(0xffffffff, s2, o);
    }
    if ((t & 31) == 0) {
        atomicAdd(&cmean[b * 3 + 0], s0);
        atomicAdd(&cmean[b * 3 + 1], s1);
        atomicAdd(&cmean[b * 3 + 2], s2);
    }
}

__global__ void coord_max_p(const float* __restrict__ coords, const float* __restrict__ cmean,
                            unsigned* __restrict__ cmaxb) {
    int b = blockIdx.y;
    int n0 = blockIdx.x * 512;
    int t = threadIdx.x;
    float invn = 1.0f / (float)NP;
    float mx = cmean[b * 3 + 0] * invn, my = cmean[b * 3 + 1] * invn, mz = cmean[b * 3 + 2] * invn;
    float m = 0.0f;
    for (int n = n0 + t; n < n0 + 512; n += 256) {
        float dx = coords[(b * 3 + 0) * NP + n] - mx;
        float dy = coords[(b * 3 + 1) * NP + n] - my;
        float dz = coords[(b * 3 + 2) * NP + n] - mz;
        m = fmaxf(m, dx * dx + dy * dy + dz * dz);
    }
#pragma unroll
    for (int o = 16; o > 0; o >>= 1) m = fmaxf(m, __shfl_xor_sync(0xffffffff, m, o));
    if ((t & 31) == 0) atomicMax(&cmaxb[b], __float_as_uint(m));
}

// ---------------- voxelize scatter (red.v4: 16 threads/point, 4 ch each) ---
__global__ void scatter(const float* __restrict__ coords, const float* __restrict__ fT,
                        const float* __restrict__ cmean, const unsigned* __restrict__ cmaxb,
                        float* __restrict__ normc, float* __restrict__ tmp,
                        float* __restrict__ cnt) {
    int t = threadIdx.x;
    int pi = blockIdx.x * 16 + (t >> 4);
    int j = t & 15;
    int b = pi / NP;
    int n = pi - b * NP;

    float invn = 1.0f / (float)NP;
    float r = sqrtf(__uint_as_float(cmaxb[b]));
    float inv = 1.0f / (2.0f * r + VOXEPS);
    float nx = (coords[(b * 3 + 0) * NP + n] - cmean[b * 3 + 0] * invn) * inv + 0.5f;
    float ny = (coords[(b * 3 + 1) * NP + n] - cmean[b * 3 + 1] * invn) * inv + 0.5f;
    float nz = (coords[(b * 3 + 2) * NP + n] - cmean[b * 3 + 2] * invn) * inv + 0.5f;
    nx = fminf(fmaxf(nx * (float)RR, 0.0f), (float)(RR - 1));
    ny = fminf(fmaxf(ny * (float)RR, 0.0f), (float)(RR - 1));
    nz = fminf(fmaxf(nz * (float)RR, 0.0f), (float)(RR - 1));
    int vx = __float2int_rn(nx), vy = __float2int_rn(ny), vz = __float2int_rn(nz);
    int v = (vx * RR + vy) * RR + vz;

    float4 f = *(const float4*)(fT + ((size_t)b * NP + n) * CC + j * 4);
    float* dst = tmp + ((size_t)b * NV + v) * CC + j * 4;
    asm volatile("red.global.add.v4.f32 [%0], {%1,%2,%3,%4};"
                 :: "l"(dst), "f"(f.x), "f"(f.y), "f"(f.z), "f"(f.w) : "memory");
    if (j == 0) atomicAdd(&cnt[b * NV + v], 1.0f);
    if (j < 3) normc[(b * 3 + j) * NP + n] = (j == 0 ? nx : (j == 1 ? ny : nz));
}

// ================= fp16 mma.sync conv (m16n8k16, quad-buffered W) ==========
#define LDS32(dst, addr) asm volatile("ld.shared.b32 %0, [%1];" : "=r"(dst) : "r"(addr))
#define MMA_F16(d, a0, a1, a2, a3, b0, b1)                                    \
    asm volatile(                                                             \
        "mma.sync.aligned.m16n8k16.row.col.f32.f16.f16.f32 "                  \
        "{%0,%1,%2,%3}, {%4,%5,%6,%7}, {%8,%9}, {%0,%1,%2,%3};"               \
        : "+f"(d[0]), "+f"(d[1]), "+f"(d[2]), "+f"(d[3])                      \
        : "r"(a0), "r"(a1), "r"(a2), "r"(a3), "r"(b0), "r"(b1))

#define CWF 1280          // W' u32 per buffer: 64 n-rows x 20
#define CSLAB 12240       // slab u32: 612 rows x 20
#define RES_PITCH 68
#define CONV_DYN ((4 * CWF + CSLAB) * 4)   // 69440 B (4 W buffers)

template <int INMODE>
__global__ __launch_bounds__(256, 3)
void conv3d_mma(const float* __restrict__ in, const float* __restrict__ cnt,
                float* __restrict__ out,
                const float* __restrict__ w, const float* __restrict__ bias,
                const float* __restrict__ insc, const float* __restrict__ insh,
                float* __restrict__ gsum, float* __restrict__ gsumsq) {
    extern __shared__ __align__(16) float dsm[];
    __shared__ float sc_sm[64], sh_sm[64], bias_sm[64];

    unsigned* wsmb = (unsigned*)dsm;           // 4 buffers of CWF
    unsigned* slab = (unsigned*)dsm + 4 * CWF;
    float* res = (float*)slab;  // reused after compute (128 x 68 <= 12240)

    int b = blockIdx.z, z0 = blockIdx.y, y0 = blockIdx.x * 4;
    int t = threadIdx.x, lane = t & 31, wid = t >> 5;
    int wy = wid >> 1, wn = wid & 1;
    int gid = lane >> 2, tig = lane & 3;

    unsigned slab_s = (unsigned)__cvta_generic_to_shared(slab);
    unsigned wsm_s0 = (unsigned)__cvta_generic_to_shared(wsmb);

    if (t < 64) {
        bias_sm[t] = bias[t];
        if (INMODE == 2) { sc_sm[t] = insc[t]; sh_sm[t] = insh[t]; }
    }
    __syncthreads();

    float acc[2][4][4];
#pragma unroll
    for (int mt = 0; mt < 2; mt++)
#pragma unroll
        for (int nt = 0; nt < 4; nt++)
#pragma unroll
            for (int e = 0; e < 4; e++) acc[mt][nt][e] = 0.0f;

    // slab: row r = (zs*6+ys)*34+xs, 16 half2 (32 ci) per row, pitch 20 u32
    auto load_slab = [&](int cig) {
        for (int i = t; i < 4896; i += 256) {
            int zy = i / 272, r = i - zy * 272;
            int c4 = r / 34, xs = r - c4 * 34;
            int zs = zy / 6, ys = zy - zs * 6;
            int zg = z0 - 1 + zs, yg = y0 - 1 + ys, xg = xs - 1;
            bool ok = (unsigned)zg < 32u && (unsigned)yg < 32u && (unsigned)xg < 32u;
            int vox = zg * 1024 + yg * 32 + xg;
            float4 v;
            if (INMODE == 0) {
                float4 sums = ok ? __ldg((const float4*)(in + ((size_t)b * NV + vox) * CC
                                                          + cig * 32 + c4 * 4))
                                 : make_float4(0.f, 0.f, 0.f, 0.f);
                float inv = ok ? 1.0f / fmaxf(__ldg(cnt + (size_t)b * NV + vox), 1.0f) : 0.0f;
                v.x = sums.x * inv; v.y = sums.y * inv;
                v.z = sums.z * inv; v.w = sums.w * inv;
            } else {
                v = ok ? __ldg((const float4*)(in + ((size_t)b * NV + vox) * CC
                                                + cig * 32 + c4 * 4))
                       : make_float4(0.f, 0.f, 0.f, 0.f);
                int c = cig * 32 + c4 * 4;
                float u;
                u = fmaf(v.x, sc_sm[c + 0], sh_sm[c + 0]); v.x = u >= 0 ? u : ALPHA * u;
                u = fmaf(v.y, sc_sm[c + 1], sh_sm[c + 1]); v.y = u >= 0 ? u : ALPHA * u;
                u = fmaf(v.z, sc_sm[c + 2], sh_sm[c + 2]); v.z = u >= 0 ? u : ALPHA * u;
                u = fmaf(v.w, sc_sm[c + 3], sh_sm[c + 3]); v.w = u >= 0 ? u : ALPHA * u;
                if (!ok) v = make_float4(0.f, 0.f, 0.f, 0.f);  // pad AFTER transform
            }
            __half2 h0 = __floats2half2_rn(v.x, v.y);
            __half2 h1 = __floats2half2_rn(v.z, v.w);
            uint2 uu;
            uu.x = *(unsigned*)&h0;
            uu.y = *(unsigned*)&h1;
            int row = (zs * 6 + ys) * 34 + xs;
            *(uint2*)(slab + row * 20 + c4 * 2) = uu;
        }
    };

    // stage weights for koff into buffer (prefetch + convert + STS, no carry)
    auto w_stage = [&](int cig, int koff, int buf) {
        const float* wb = w + (size_t)(koff * 64 + cig * 32) * 64;
        unsigned* dst = wsmb + buf * CWF;
#pragma unroll
        for (int jj = 0; jj < 4; jj++) {
            int e = t + jj * 256;
            int k2 = e >> 6, co = e & 63;
            float lo = __ldg(wb + (size_t)(2 * k2) * 64 + co);
            float hi = __ldg(wb + (size_t)(2 * k2 + 1) * 64 + co);
            __half2 h = __floats2half2_rn(lo, hi);
            dst[co * 20 + k2] = *(unsigned*)&h;
        }
    };

    auto compute = [&](int buf, int koff) {
        int dz = koff / 9, rem = koff - dz * 9;
        int dy = rem / 3, dx = rem - dy * 3;
        unsigned a_base = slab_s +
            (unsigned)((((dz * 6 + wy + dy) * 34) + gid + dx) * 20 + tig) * 4;
        unsigned b_base = wsm_s0 + (unsigned)buf * (CWF * 4) +
                          (unsigned)((wn * 32 + gid) * 20 + tig) * 4;
#pragma unroll
        for (int ks = 0; ks < 2; ks++) {
            unsigned ab = a_base + ks * 32;
            unsigned bb = b_base + ks * 32;
            unsigned a0, a1, a2, a3, a4, a5, a6, a7;
            LDS32(a0, ab);            LDS32(a1, ab + 640);
            LDS32(a2, ab + 16);       LDS32(a3, ab + 656);
            LDS32(a4, ab + 1280);     LDS32(a5, ab + 1920);
            LDS32(a6, ab + 1296);     LDS32(a7, ab + 1936);
            unsigned b0[4], b1[4];
#pragma unroll
            for (int nt = 0; nt < 4; nt++) {
                LDS32(b0[nt], bb + nt * 640);
                LDS32(b1[nt], bb + nt * 640 + 16);
            }
#pragma unroll
            for (int nt = 0; nt < 4; nt++) {
                MMA_F16(acc[0][nt], a0, a1, a2, a3, b0[nt], b1[nt]);
                MMA_F16(acc[1][nt], a4, a5, a6, a7, b0[nt], b1[nt]);
            }
        }
    };

    // quad-buffered main loop: sync every 2 koffs.
    // invariant at period start [k, k+1] (after sync): bufs k%4, (k+1)%4 ready;
    // all computes <= k-1 done, so bufs (k+2)%4, (k+3)%4 are free to restage.
#pragma unroll 1
    for (int cig = 0; cig < 2; cig++) {
        load_slab(cig);
        w_stage(cig, 0, 0);
        w_stage(cig, 1, 1);
        __syncthreads();
#pragma unroll 1
        for (int k = 0; k < 26; k += 2) {
            compute(k & 3, k);
            compute((k + 1) & 3, k + 1);
            if (k + 2 < 27) w_stage(cig, k + 2, (k + 2) & 3);
            if (k + 3 < 27) w_stage(cig, k + 3, (k + 3) & 3);
            __syncthreads();
        }
        compute(26 & 3, 26);   // koff 26 (tail)
        __syncthreads();       // protect slab (cig=0) / res reuse (cig=1)
    }

    // ---- epilogue ----
#pragma unroll
    for (int mt = 0; mt < 2; mt++)
#pragma unroll
        for (int nt = 0; nt < 4; nt++) {
            int spat0 = wy * 32 + mt * 16 + gid;
            int cout0 = wn * 32 + nt * 8 + tig * 2;
            *(float2*)(res + spat0 * RES_PITCH + cout0) =
                make_float2(acc[mt][nt][0], acc[mt][nt][1]);
            *(float2*)(res + (spat0 + 8) * RES_PITCH + cout0) =
                make_float2(acc[mt][nt][2], acc[mt][nt][3]);
        }
    __syncthreads();

    {
        int s_ = t >> 1, h = t & 1;
        int vox = z0 * 1024 + (y0 + (s_ >> 5)) * 32 + (s_ & 31);
        float* op = out + ((size_t)b * NV + vox) * CC + h * 32;
        const float* rp = res + s_ * RES_PITCH + h * 32;
#pragma unroll
        for (int k = 0; k < 8; k++) {
            float4 v;
            v.x = rp[4 * k + 0] + bias_sm[h * 32 + 4 * k + 0];
            v.y = rp[4 * k + 1] + bias_sm[h * 32 + 4 * k + 1];
            v.z = rp[4 * k + 2] + bias_sm[h * 32 + 4 * k + 2];
            v.w = rp[4 * k + 3] + bias_sm[h * 32 + 4 * k + 3];
            *(float4*)(op + 4 * k) = v;
        }
    }
#pragma unroll
    for (int j = 0; j < 8; j++) {
        int c = wid * 8 + j;
        float bval = bias_sm[c];
        float s = 0, q = 0;
#pragma unroll
        for (int sy = 0; sy < 4; sy++) {
            float v = res[(sy * 32 + lane) * RES_PITCH + c] + bval;
            s += v; q += v * v;
        }
#pragma unroll
        for (int o = 16; o > 0; o >>= 1) {
            s += __shfl_xor_sync(0xffffffff, s, o);
            q += __shfl_xor_sync(0xffffffff, q, o);
        }
        if (lane == 0) { atomicAdd(&gsum[c], s); atomicAdd(&gsumsq[c], q); }
    }
}

// ================= fp16 mma.sync point GEMM + fused stats ===================
#define PGA_U32 (128 * 36)   // 4608
#define PGW_U32 (64 * 36)    // 2304
#define PG_DYN ((PGA_U32 + PGW_U32) * 4 + 128 * RES_PITCH * 4)  // 62464 B

__global__ __launch_bounds__(256, 2)
void pgemm_mma(const float* __restrict__ fT, const float* __restrict__ w,
               const float* __restrict__ bias, float* __restrict__ pT,
               float* __restrict__ gsum, float* __restrict__ gsumsq) {
    extern __shared__ __align__(16) float dsm[];
    __shared__ float bias_sm[64];
    unsigned* asm0 = (unsigned*)dsm;            // [128][36]
    unsigned* wsm0 = (unsigned*)dsm + PGA_U32;  // [64][36]
    float* res = dsm;                           // reuse after compute

    int b = blockIdx.y;
    int n0 = blockIdx.x * 128;
    int t = threadIdx.x, lane = t & 31, wid = t >> 5;
    int wy = wid >> 1, wn = wid & 1;
    int gid = lane >> 2, tig = lane & 3;

    unsigned a_s = (unsigned)__cvta_generic_to_shared(asm0);
    unsigned w_s = (unsigned)__cvta_generic_to_shared(wsm0);

    if (t < 64) bias_sm[t] = bias[t];

    for (int i = t; i < 2048; i += 256) {      // 128 n x 16 c4
        int n = i >> 4, c4 = i & 15;
        float4 v = __ldg((const float4*)(fT + ((size_t)b * NP + n0 + n) * CC + c4 * 4));
        __half2 h0 = __floats2half2_rn(v.x, v.y);
        __half2 h1 = __floats2half2_rn(v.z, v.w);
        uint2 uu;
        uu.x = *(unsigned*)&h0;
        uu.y = *(unsigned*)&h1;
        *(uint2*)(asm0 + n * 36 + c4 * 2) = uu;
    }
    for (int i = t; i < 2048; i += 256) {      // 64 co x 32 k2
        int co = i >> 5, k2 = i & 31;
        float lo = __ldg(w + (size_t)(2 * k2) * 64 + co);
        float hi = __ldg(w + (size_t)(2 * k2 + 1) * 64 + co);
        __half2 h = __floats2half2_rn(lo, hi);
        wsm0[co * 36 + k2] = *(unsigned*)&h;
    }
    __syncthreads();

    float acc[2][4][4];
#pragma unroll
    for (int mt = 0; mt < 2; mt++)
#pragma unroll
        for (int nt = 0; nt < 4; nt++)
#pragma unroll
            for (int e = 0; e < 4; e++) acc[mt][nt][e] = 0.0f;

    unsigned a_base = a_s + (unsigned)((wy * 32 + gid) * 36 + tig) * 4;
    unsigned b_base = w_s + (unsigned)((wn * 32 + gid) * 36 + tig) * 4;
#pragma unroll
    for (int ks = 0; ks < 4; ks++) {
        unsigned ab = a_base + ks * 32;
        unsigned bb = b_base + ks * 32;
        unsigned a0, a1, a2, a3, a4, a5, a6, a7;
        LDS32(a0, ab);            LDS32(a1, ab + 1152);
        LDS32(a2, ab + 16);       LDS32(a3, ab + 1168);
        LDS32(a4, ab + 2304);     LDS32(a5, ab + 3456);
        LDS32(a6, ab + 2320);     LDS32(a7, ab + 3472);
        unsigned b0[4], b1[4];
#pragma unroll
        for (int nt = 0; nt < 4; nt++) {
            LDS32(b0[nt], bb + nt * 1152);
            LDS32(b1[nt], bb + nt * 1152 + 16);
        }
#pragma unroll
        for (int nt = 0; nt < 4; nt++) {
            MMA_F16(acc[0][nt], a0, a1, a2, a3, b0[nt], b1[nt]);
            MMA_F16(acc[1][nt], a4, a5, a6, a7, b0[nt], b1[nt]);
        }
    }
    __syncthreads();

#pragma unroll
    for (int mt = 0; mt < 2; mt++)
#pragma unroll
        for (int nt = 0; nt < 4; nt++) {
            int spat0 = wy * 32 + mt * 16 + gid;
            int cout0 = wn * 32 + nt * 8 + tig * 2;
            *(float2*)(res + spat0 * RES_PITCH + cout0) =
                make_float2(acc[mt][nt][0], acc[mt][nt][1]);
            *(float2*)(res + (spat0 + 8) * RES_PITCH + cout0) =
                make_float2(acc[mt][nt][2], acc[mt][nt][3]);
        }
    __syncthreads();

    {
        int s_ = t >> 1, h = t & 1;
        float* op = pT + ((size_t)b * NP + n0 + s_) * CC + h * 32;
        const float* rp = res + s_ * RES_PITCH + h * 32;
#pragma unroll
        for (int k = 0; k < 8; k++) {
            float4 v;
            v.x = rp[4 * k + 0] + bias_sm[h * 32 + 4 * k + 0];
            v.y = rp[4 * k + 1] + bias_sm[h * 32 + 4 * k + 1];
            v.z = rp[4 * k + 2] + bias_sm[h * 32 + 4 * k + 2];
            v.w = rp[4 * k + 3] + bias_sm[h * 32 + 4 * k + 3];
            *(float4*)(op + 4 * k) = v;
        }
    }
#pragma unroll
    for (int j = 0; j < 8; j++) {
        int c = wid * 8 + j;
        float bval = bias_sm[c];
        float s = 0, q = 0;
#pragma unroll
        for (int sy = 0; sy < 4; sy++) {
            float v = res[(sy * 32 + lane) * RES_PITCH + c] + bval;
            s += v; q += v * v;
        }
#pragma unroll
        for (int o = 16; o > 0; o >>= 1) {
            s += __shfl_xor_sync(0xffffffff, s, o);
            q += __shfl_xor_sync(0xffffffff, q, o);
        }
        if (lane == 0) { atomicAdd(&gsum[c], s); atomicAdd(&gsumsq[c], q); }
    }
}

// ---------------- final: devox(BN2+lrelu on the fly) + BN(p)+lrelu + add ----
__global__ void final_k(const float* __restrict__ vT, const float* __restrict__ pT,
                        const float* __restrict__ normc,
                        const float* __restrict__ sc2, const float* __restrict__ sh2,
                        const float* __restrict__ scp, const float* __restrict__ shp,
                        float* __restrict__ out) {
    __shared__ float res[64][65];
    __shared__ int cidx[64][8];
    __shared__ float cw[64][8];
    int b = blockIdx.y;
    int n0 = blockIdx.x * 64;
    int t = threadIdx.x;

    if (t < 64) {
        int n = n0 + t;
        float xs = normc[(b * 3 + 0) * NP + n];
        float ys = normc[(b * 3 + 1) * NP + n];
        float zs = normc[(b * 3 + 2) * NP + n];
        float x0f = floorf(xs), y0f = floorf(ys), z0f = floorf(zs);
        float fx = xs - x0f, fy = ys - y0f, fz = zs - z0f;
        int x0 = (int)x0f, y0 = (int)y0f, z0 = (int)z0f;
        int x1 = min(x0 + 1, 31), y1 = min(y0 + 1, 31), z1 = min(z0 + 1, 31);
#pragma unroll
        for (int k = 0; k < 8; k++) {
            int dx = (k >> 2) & 1, dy = (k >> 1) & 1, dz = k & 1;
            float wt = (dx ? fx : 1.0f - fx) * (dy ? fy : 1.0f - fy) * (dz ? fz : 1.0f - fz);
            int idx = ((dx ? x1 : x0) * 32 + (dy ? y1 : y0)) * 32 + (dz ? z1 : z0);
            cidx[t][k] = idx;
            cw[t][k] = wt;
        }
    }
    __syncthreads();

    int c = t & 63, ty = t >> 6;
    float sc2v = sc2[c], sh2v = sh2[c];
    float scpv = scp[c], shpv = shp[c];

    for (int j = ty; j < 64; j += 8) {
        int j2 = j + 4;
        float acc0 = 0.0f, acc1 = 0.0f;
#pragma unroll
        for (int k = 0; k < 8; k++) {
            float g0 = vT[((size_t)b * NV + cidx[j][k]) * CC + c];
            float g1 = vT[((size_t)b * NV + cidx[j2][k]) * CC + c];
            float u0 = fmaf(g0, sc2v, sh2v);
            float u1 = fmaf(g1, sc2v, sh2v);
            u0 = u0 >= 0 ? u0 : ALPHA * u0;
            u1 = u1 >= 0 ? u1 : ALPHA * u1;
            acc0 += cw[j][k] * u0;
            acc1 += cw[j2][k] * u1;
        }
        float pv0 = fmaf(pT[((size_t)b * NP + n0 + j) * CC + c], scpv, shpv);
        float pv1 = fmaf(pT[((size_t)b * NP + n0 + j2) * CC + c], scpv, shpv);
        pv0 = pv0 >= 0 ? pv0 : ALPHA * pv0;
        pv1 = pv1 >= 0 ? pv1 : ALPHA * pv1;
        res[c][j] = acc0 + pv0;
        res[c][j2] = acc1 + pv1;
    }
    __syncthreads();

    for (int i = t; i < 4096; i += 256) {
        int c2 = i >> 6, j = i & 63;
        out[((size_t)b * CC + c2) * NP + n0 + j] = res[c2][j];
    }
}

// ---------------- launcher ----------------
extern "C" void kernel_launch(void* const* d_in, const int* in_sizes, int n_in,
                              void* d_out, int out_size) {
    const float* feat   = (const float*)d_in[0];
    const float* coords = (const float*)d_in[1];
    const float* c1w    = (const float*)d_in[2];
    const float* c1b    = (const float*)d_in[3];
    const float* g1     = (const float*)d_in[4];
    const float* b1     = (const float*)d_in[5];
    const float* c2w    = (const float*)d_in[6];
    const float* c2b    = (const float*)d_in[7];
    const float* g2     = (const float*)d_in[8];
    const float* b2     = (const float*)d_in[9];
    const float* pw     = (const float*)d_in[10];
    const float* pb     = (const float*)d_in[11];
    const float* pg     = (const float*)d_in[12];
    const float* pbeta  = (const float*)d_in[13];
    float* out = (float*)d_out;

    float *fT, *tmp, *cnt, *bufB, *pT, *normc, *cmean, *stats, *scsh;
    unsigned* cmaxb;
    cudaGetSymbolAddress((void**)&fT, g_fT);
    cudaGetSymbolAddress((void**)&tmp, g_tmp);
    cudaGetSymbolAddress((void**)&cnt, g_cnt);
    cudaGetSymbolAddress((void**)&bufB, g_bufB);
    cudaGetSymbolAddress((void**)&pT, g_pT);
    cudaGetSymbolAddress((void**)&normc, g_normc);
    cudaGetSymbolAddress((void**)&cmean, g_cmean);
    cudaGetSymbolAddress((void**)&cmaxb, g_cmaxb);
    cudaGetSymbolAddress((void**)&stats, g_stats);
    cudaGetSymbolAddress((void**)&scsh, g_scsh);

    float* sum1 = stats + 0 * CC;  float* sq1 = stats + 1 * CC;
    float* sum2 = stats + 2 * CC;  float* sq2 = stats + 3 * CC;
    float* psum = stats + 4 * CC;  float* psq = stats + 5 * CC;
    float* sc1 = scsh + 0 * CC;    float* sh1 = scsh + 1 * CC;
    float* sc2 = scsh + 2 * CC;    float* sh2 = scsh + 3 * CC;
    float* scp = scsh + 4 * CC;    float* shp = scsh + 5 * CC;

    cudaFuncSetAttribute(conv3d_mma<0>, cudaFuncAttributeMaxDynamicSharedMemorySize, CONV_DYN);
    cudaFuncSetAttribute(conv3d_mma<2>, cudaFuncAttributeMaxDynamicSharedMemorySize, CONV_DYN);
    cudaFuncSetAttribute(pgemm_mma, cudaFuncAttributeMaxDynamicSharedMemorySize, PG_DYN);

    const float invV = 1.0f / (float)(BB * NV);
    const float invP = 1.0f / (float)(BB * NP);

    // voxelize
    zero_all<<<4096, 256>>>(tmp, cnt, stats, cmean, cmaxb);
    transpose_feat<<<dim3(NP / 32, BB), 256>>>(feat, fT);
    coord_mean_p<<<dim3(32, BB), 256>>>(coords, cmean);
    coord_max_p<<<dim3(32, BB), 256>>>(coords, cmean, cmaxb);
    scatter<<<BB * NP / 16, 256>>>(coords, fT, cmean, cmaxb, normc, tmp, cnt);

    // conv1: voxel sums+counts in (finalize fused), channels-last out
    conv3d_mma<0><<<dim3(8, 32, BB), 256, CONV_DYN>>>(tmp, cnt, bufB, c1w, c1b,
                                                      nullptr, nullptr, sum1, sq1);
    mkscale<<<1, 64>>>(sum1, sq1, g1, b1, invV, sc1, sh1);

    // conv2: channels-last in with BN1+lrelu fused, channels-last out into tmp
    conv3d_mma<2><<<dim3(8, 32, BB), 256, CONV_DYN>>>(bufB, nullptr, tmp, c2w, c2b,
                                                      sc1, sh1, sum2, sq2);
    mkscale<<<1, 64>>>(sum2, sq2, g2, b2, invV, sc2, sh2);

    // point branch: fp16 tensor-core GEMM + fused stats
    pgemm_mma<<<dim3(NP / 128, BB), 256, PG_DYN>>>(fT, pw, pb, pT, psum, psq);
    mkscale<<<1, 64>>>(psum, psq, pg, pbeta, invP, scp, shp);

    // devoxelize (BN2+lrelu applied on gather) + point BN + add
    final_k<<<dim3(NP / 64, BB), 256>>>(tmp, pT, normc, sc2, sh2, scp, shp, out);

    // coords passthrough (second tuple output), if the harness expects it
    int main_sz = BB * CC * NP;
    int coord_sz = BB * 3 * NP;
    if (out_size >= main_sz + coord_sz)
        copy_kernel<<<coord_sz / 256, 256>>>(coords, out + main_sz, coord_sz);
}

// round 16
// speedup vs baseline: 1.0270x; 1.0270x over previous
#include <cuda_runtime.h>
#include <cuda_fp16.h>

#define BB 8
#define CC 64
#define NP 16384
#define RR 32
#define NV 32768          // 32^3
#define ALPHA 0.1f
#define BNEPS 1e-4f
#define VOXEPS 1e-6f

// ---------------- scratch (device globals; no allocation allowed) ----------
__device__ float g_fT[BB * NP * CC];        // features transposed [b][n][c]
__device__ float g_tmp[BB * NV * CC];       // voxel sums [b][v][c]; later raw conv2 out
__device__ float g_cnt[BB * NV];            // voxel counts
__device__ float g_bufB[BB * CC * NV];      // conv1 output (channels-last [b][v][c])
__device__ float g_pT[BB * NP * CC];        // point branch [b][n][c]
__device__ float g_normc[BB * 3 * NP];      // normalized coords in [0,31]
__device__ float g_cmean[BB * 3];           // coordinate SUMS
__device__ unsigned g_cmaxb[BB];            // max dist^2 as float bits
__device__ float g_stats[6 * CC];           // sum1,sq1,sum2,sq2,psum,psq
__device__ float g_scsh[6 * CC];            // sc1,sh1,sc2,sh2,scp,shp

// ---------------- utility kernels ----------------
// zero tmp + cnt + stats + cmean + cmaxb in ONE launch
__global__ void zero_all(float* tmp, float* cnt, float* stats, float* cmean,
                         unsigned* cmaxb) {
    size_t i = (size_t)blockIdx.x * blockDim.x + threadIdx.x;
    size_t stride = (size_t)gridDim.x * blockDim.x;
    const size_t ntmp = (size_t)BB * NV * CC;
    for (size_t k = i; k < ntmp; k += stride) tmp[k] = 0.0f;
    for (size_t k = i; k < (size_t)BB * NV; k += stride) cnt[k] = 0.0f;
    if (i < 6 * CC) stats[i] = 0.0f;
    if (i < BB * 3) cmean[i] = 0.0f;
    if (i < BB) cmaxb[i] = 0u;
}

__global__ void copy_kernel(const float* __restrict__ src, float* __restrict__ dst, int n) {
    int i = blockIdx.x * blockDim.x + threadIdx.x;
    int stride = gridDim.x * blockDim.x;
    for (; i < n; i += stride) dst[i] = src[i];
}

__global__ void mkscale(const float* __restrict__ sum, const float* __restrict__ sumsq,
                        const float* __restrict__ gamma, const float* __restrict__ beta,
                        float invcnt, float* __restrict__ sc, float* __restrict__ sh) {
    int c = threadIdx.x;
    float mean = sum[c] * invcnt;
    float var = sumsq[c] * invcnt - mean * mean;
    float s = gamma[c] * rsqrtf(var + BNEPS);
    sc[c] = s;
    sh[c] = beta[c] - mean * s;
}

// ---------------- features transpose [b][c][n] -> [b][n][c] ----------------
__global__ void transpose_feat(const float* __restrict__ feat, float* __restrict__ fT) {
    __shared__ float s[CC][33];
    int b = blockIdx.y;
    int n0 = blockIdx.x * 32;
    int t = threadIdx.x;
    for (int i = t; i < 32 * 64; i += 256) {
        int c = i >> 5, n = i & 31;
        s[c][n] = feat[(b * CC + c) * NP + n0 + n];
    }
    __syncthreads();
    for (int i = t; i < 32 * 64; i += 256) {
        int n = i >> 6, c = i & 63;
        fT[((size_t)b * NP + n0 + n) * CC + c] = s[c][n];
    }
}

// ---------------- coord statistics ----------------
__global__ void coord_mean_p(const float* __restrict__ coords, float* __restrict__ cmean) {
    int b = blockIdx.y;
    int n0 = blockIdx.x * 512;
    int t = threadIdx.x;
    float s0 = 0, s1 = 0, s2 = 0;
    for (int n = n0 + t; n < n0 + 512; n += 256) {
        s0 += coords[(b * 3 + 0) * NP + n];
        s1 += coords[(b * 3 + 1) * NP + n];
        s2 += coords[(b * 3 + 2) * NP + n];
    }
#pragma unroll
    for (int o = 16; o > 0; o >>= 1) {
        s0 += __shfl_xor_sync(0xffffffff, s0, o);
        s1 += __shfl_xor_sync(0xffffffff, s1, o);
        s2 += __shfl_xor_sync(0xffffffff, s2, o);
    }
    if ((t & 31) == 0) {
        atomicAdd(&cmean[b * 3 + 0], s0);
        atomicAdd(&cmean[b * 3 + 1], s1);
        atomicAdd(&cmean[b * 3 + 2], s2);
    }
}

__global__ void coord_max_p(const float* __restrict__ coords, const float* __restrict__ cmean,
                            unsigned* __restrict__ cmaxb) {
    int b = blockIdx.y;
    int n0 = blockIdx.x * 512;
    int t = threadIdx.x;
    float invn = 1.0f / (float)NP;
    float mx = cmean[b * 3 + 0] * invn, my = cmean[b * 3 + 1] * invn, mz = cmean[b * 3 + 2] * invn;
    float m = 0.0f;
    for (int n = n0 + t; n < n0 + 512; n += 256) {
        float dx = coords[(b * 3 + 0) * NP + n] - mx;
        float dy = coords[(b * 3 + 1) * NP + n] - my;
        float dz = coords[(b * 3 + 2) * NP + n] - mz;
        m = fmaxf(m, dx * dx + dy * dy + dz * dz);
    }
#pragma unroll
    for (int o = 16; o > 0; o >>= 1) m = fmaxf(m, __shfl_xor_sync(0xffffffff, m, o));
    if ((t & 31) == 0) atomicMax(&cmaxb[b], __float_as_uint(m));
}

// ---------------- voxelize scatter (red.v4: 16 threads/point, 4 ch each) ---
__global__ void scatter(const float* __restrict__ coords, const float* __restrict__ fT,
                        const float* __restrict__ cmean, const unsigned* __restrict__ cmaxb,
                        float* __restrict__ normc, float* __restrict__ tmp,
                        float* __restrict__ cnt) {
    int t = threadIdx.x;
    int pi = blockIdx.x * 16 + (t >> 4);
    int j = t & 15;
    int b = pi / NP;
    int n = pi - b * NP;

    float invn = 1.0f / (float)NP;
    float r = sqrtf(__uint_as_float(cmaxb[b]));
    float inv = 1.0f / (2.0f * r + VOXEPS);
    float nx = (coords[(b * 3 + 0) * NP + n] - cmean[b * 3 + 0] * invn) * inv + 0.5f;
    float ny = (coords[(b * 3 + 1) * NP + n] - cmean[b * 3 + 1] * invn) * inv + 0.5f;
    float nz = (coords[(b * 3 + 2) * NP + n] - cmean[b * 3 + 2] * invn) * inv + 0.5f;
    nx = fminf(fmaxf(nx * (float)RR, 0.0f), (float)(RR - 1));
    ny = fminf(fmaxf(ny * (float)RR, 0.0f), (float)(RR - 1));
    nz = fminf(fmaxf(nz * (float)RR, 0.0f), (float)(RR - 1));
    int vx = __float2int_rn(nx), vy = __float2int_rn(ny), vz = __float2int_rn(nz);
    int v = (vx * RR + vy) * RR + vz;

    float4 f = *(const float4*)(fT + ((size_t)b * NP + n) * CC + j * 4);
    float* dst = tmp + ((size_t)b * NV + v) * CC + j * 4;
    asm volatile("red.global.add.v4.f32 [%0], {%1,%2,%3,%4};"
                 :: "l"(dst), "f"(f.x), "f"(f.y), "f"(f.z), "f"(f.w) : "memory");
    if (j == 0) atomicAdd(&cnt[b * NV + v], 1.0f);
    if (j < 3) normc[(b * 3 + j) * NP + n] = (j == 0 ? nx : (j == 1 ? ny : nz));
}

// ================= fp16 mma.sync conv (m16n8k16, R14 double-buffer) ========
#define LDS32(dst, addr) asm volatile("ld.shared.b32 %0, [%1];" : "=r"(dst) : "r"(addr))
#define MMA_F16(d, a0, a1, a2, a3, b0, b1)                                    \
    asm volatile(                                                             \
        "mma.sync.aligned.m16n8k16.row.col.f32.f16.f16.f32 "                  \
        "{%0,%1,%2,%3}, {%4,%5,%6,%7}, {%8,%9}, {%0,%1,%2,%3};"               \
        : "+f"(d[0]), "+f"(d[1]), "+f"(d[2]), "+f"(d[3])                      \
        : "r"(a0), "r"(a1), "r"(a2), "r"(a3), "r"(b0), "r"(b1))

#define CWF 1280          // W' u32 per buffer: 64 n-rows x 20
#define CSLAB 12240       // slab u32: 612 rows x 20
#define RES_PITCH 68
#define CONV_DYN ((2 * CWF + CSLAB) * 4)   // 59200 B

template <int INMODE>
__global__ __launch_bounds__(256, 3)
void conv3d_mma(const float* __restrict__ in, const float* __restrict__ cnt,
                float* __restrict__ out,
                const float* __restrict__ w, const float* __restrict__ bias,
                const float* __restrict__ insc, const float* __restrict__ insh,
                float* __restrict__ gsum, float* __restrict__ gsumsq) {
    extern __shared__ __align__(16) float dsm[];
    __shared__ float sc_sm[64], sh_sm[64], bias_sm[64];

    unsigned* wsm0 = (unsigned*)dsm;
    unsigned* wsm1 = (unsigned*)dsm + CWF;
    unsigned* slab = (unsigned*)dsm + 2 * CWF;
    float* res = (float*)slab;  // reused after compute (128 x 68 <= 12240)

    int b = blockIdx.z, z0 = blockIdx.y, y0 = blockIdx.x * 4;
    int t = threadIdx.x, lane = t & 31, wid = t >> 5;
    int wy = wid >> 1, wn = wid & 1;
    int gid = lane >> 2, tig = lane & 3;

    unsigned slab_s = (unsigned)__cvta_generic_to_shared(slab);
    unsigned wsm_s[2] = {(unsigned)__cvta_generic_to_shared(wsm0),
                         (unsigned)__cvta_generic_to_shared(wsm1)};

    if (t < 64) {
        bias_sm[t] = bias[t];
        if (INMODE == 2) { sc_sm[t] = insc[t]; sh_sm[t] = insh[t]; }
    }
    __syncthreads();

    float acc[2][4][4];
#pragma unroll
    for (int mt = 0; mt < 2; mt++)
#pragma unroll
        for (int nt = 0; nt < 4; nt++)
#pragma unroll
            for (int e = 0; e < 4; e++) acc[mt][nt][e] = 0.0f;

    // slab: row r = (zs*6+ys)*34+xs, 16 half2 (32 ci) per row, pitch 20 u32
    auto load_slab = [&](int cig) {
        for (int i = t; i < 4896; i += 256) {
            int zy = i / 272, r = i - zy * 272;
            int c4 = r / 34, xs = r - c4 * 34;
            int zs = zy / 6, ys = zy - zs * 6;
            int zg = z0 - 1 + zs, yg = y0 - 1 + ys, xg = xs - 1;
            bool ok = (unsigned)zg < 32u && (unsigned)yg < 32u && (unsigned)xg < 32u;
            int vox = zg * 1024 + yg * 32 + xg;
            float4 v;
            if (INMODE == 0) {
                float4 sums = ok ? __ldg((const float4*)(in + ((size_t)b * NV + vox) * CC
                                                          + cig * 32 + c4 * 4))
                                 : make_float4(0.f, 0.f, 0.f, 0.f);
                float inv = ok ? 1.0f / fmaxf(__ldg(cnt + (size_t)b * NV + vox), 1.0f) : 0.0f;
                v.x = sums.x * inv; v.y = sums.y * inv;
                v.z = sums.z * inv; v.w = sums.w * inv;
            } else {
                v = ok ? __ldg((const float4*)(in + ((size_t)b * NV + vox) * CC
                                                + cig * 32 + c4 * 4))
                       : make_float4(0.f, 0.f, 0.f, 0.f);
                int c = cig * 32 + c4 * 4;
                float u;
                u = fmaf(v.x, sc_sm[c + 0], sh_sm[c + 0]); v.x = u >= 0 ? u : ALPHA * u;
                u = fmaf(v.y, sc_sm[c + 1], sh_sm[c + 1]); v.y = u >= 0 ? u : ALPHA * u;
                u = fmaf(v.z, sc_sm[c + 2], sh_sm[c + 2]); v.z = u >= 0 ? u : ALPHA * u;
                u = fmaf(v.w, sc_sm[c + 3], sh_sm[c + 3]); v.w = u >= 0 ? u : ALPHA * u;
                if (!ok) v = make_float4(0.f, 0.f, 0.f, 0.f);  // pad AFTER transform
            }
            __half2 h0 = __floats2half2_rn(v.x, v.y);
            __half2 h1 = __floats2half2_rn(v.z, v.w);
            uint2 uu;
            uu.x = *(unsigned*)&h0;
            uu.y = *(unsigned*)&h1;
            int row = (zs * 6 + ys) * 34 + xs;
            *(uint2*)(slab + row * 20 + c4 * 2) = uu;
        }
    };

    float wlo[4], whi[4];
    auto w_prefetch = [&](int cig, int koff) {
        const float* wb = w + (size_t)(koff * 64 + cig * 32) * 64;
#pragma unroll
        for (int j = 0; j < 4; j++) {
            int e = t + j * 256;
            int k2 = e >> 6, co = e & 63;
            wlo[j] = __ldg(wb + (size_t)(2 * k2) * 64 + co);
            whi[j] = __ldg(wb + (size_t)(2 * k2 + 1) * 64 + co);
        }
    };
    auto w_sts = [&](unsigned* dst) {
#pragma unroll
        for (int j = 0; j < 4; j++) {
            int e = t + j * 256;
            int k2 = e >> 6, co = e & 63;
            __half2 h = __floats2half2_rn(wlo[j], whi[j]);
            dst[co * 20 + k2] = *(unsigned*)&h;
        }
    };

    auto compute = [&](int buf, int koff) {
        int dz = koff / 9, rem = koff - dz * 9;
        int dy = rem / 3, dx = rem - dy * 3;
        unsigned a_base = slab_s +
            (unsigned)((((dz * 6 + wy + dy) * 34) + gid + dx) * 20 + tig) * 4;
        unsigned b_base = wsm_s[buf] + (unsigned)((wn * 32 + gid) * 20 + tig) * 4;
#pragma unroll
        for (int ks = 0; ks < 2; ks++) {
            unsigned ab = a_base + ks * 32;
            unsigned bb = b_base + ks * 32;
            unsigned a0, a1, a2, a3, a4, a5, a6, a7;
            LDS32(a0, ab);            LDS32(a1, ab + 640);
            LDS32(a2, ab + 16);       LDS32(a3, ab + 656);
            LDS32(a4, ab + 1280);     LDS32(a5, ab + 1920);
            LDS32(a6, ab + 1296);     LDS32(a7, ab + 1936);
            unsigned b0[4], b1[4];
#pragma unroll
            for (int nt = 0; nt < 4; nt++) {
                LDS32(b0[nt], bb + nt * 640);
                LDS32(b1[nt], bb + nt * 640 + 16);
            }
#pragma unroll
            for (int nt = 0; nt < 4; nt++) {
                MMA_F16(acc[0][nt], a0, a1, a2, a3, b0[nt], b1[nt]);
                MMA_F16(acc[1][nt], a4, a5, a6, a7, b0[nt], b1[nt]);
            }
        }
    };

#pragma unroll 1
    for (int cig = 0; cig < 2; cig++) {
        load_slab(cig);
        w_prefetch(cig, 0);
        w_sts(wsm0);
        __syncthreads();
#pragma unroll 1
        for (int koff = 0; koff < 27; koff++) {
            if (koff < 26) w_prefetch(cig, koff + 1);
            compute(koff & 1, koff);
            if (koff < 26) w_sts((koff & 1) ? wsm0 : wsm1);
            __syncthreads();
        }
    }

    // ---- epilogue ----
#pragma unroll
    for (int mt = 0; mt < 2; mt++)
#pragma unroll
        for (int nt = 0; nt < 4; nt++) {
            int spat0 = wy * 32 + mt * 16 + gid;
            int cout0 = wn * 32 + nt * 8 + tig * 2;
            *(float2*)(res + spat0 * RES_PITCH + cout0) =
                make_float2(acc[mt][nt][0], acc[mt][nt][1]);
            *(float2*)(res + (spat0 + 8) * RES_PITCH + cout0) =
                make_float2(acc[mt][nt][2], acc[mt][nt][3]);
        }
    __syncthreads();

    {
        int s_ = t >> 1, h = t & 1;
        int vox = z0 * 1024 + (y0 + (s_ >> 5)) * 32 + (s_ & 31);
        float* op = out + ((size_t)b * NV + vox) * CC + h * 32;
        const float* rp = res + s_ * RES_PITCH + h * 32;
#pragma unroll
        for (int k = 0; k < 8; k++) {
            float4 v;
            v.x = rp[4 * k + 0] + bias_sm[h * 32 + 4 * k + 0];
            v.y = rp[4 * k + 1] + bias_sm[h * 32 + 4 * k + 1];
            v.z = rp[4 * k + 2] + bias_sm[h * 32 + 4 * k + 2];
            v.w = rp[4 * k + 3] + bias_sm[h * 32 + 4 * k + 3];
            *(float4*)(op + 4 * k) = v;
        }
    }
#pragma unroll
    for (int j = 0; j < 8; j++) {
        int c = wid * 8 + j;
        float bval = bias_sm[c];
        float s = 0, q = 0;
#pragma unroll
        for (int sy = 0; sy < 4; sy++) {
            float v = res[(sy * 32 + lane) * RES_PITCH + c] + bval;
            s += v; q += v * v;
        }
#pragma unroll
        for (int o = 16; o > 0; o >>= 1) {
            s += __shfl_xor_sync(0xffffffff, s, o);
            q += __shfl_xor_sync(0xffffffff, q, o);
        }
        if (lane == 0) { atomicAdd(&gsum[c], s); atomicAdd(&gsumsq[c], q); }
    }
}

// ================= fp16 mma.sync point GEMM + fused stats ===================
#define PGA_U32 (128 * 36)   // 4608
#define PGW_U32 (64 * 36)    // 2304
#define PG_DYN ((PGA_U32 + PGW_U32) * 4 + 128 * RES_PITCH * 4)  // 62464 B

__global__ __launch_bounds__(256, 2)
void pgemm_mma(const float* __restrict__ fT, const float* __restrict__ w,
               const float* __restrict__ bias, float* __restrict__ pT,
               float* __restrict__ gsum, float* __restrict__ gsumsq) {
    extern __shared__ __align__(16) float dsm[];
    __shared__ float bias_sm[64];
    unsigned* asm0 = (unsigned*)dsm;            // [128][36]
    unsigned* wsm0 = (unsigned*)dsm + PGA_U32;  // [64][36]
    float* res = dsm;                           // reuse after compute

    int b = blockIdx.y;
    int n0 = blockIdx.x * 128;
    int t = threadIdx.x, lane = t & 31, wid = t >> 5;
    int wy = wid >> 1, wn = wid & 1;
    int gid = lane >> 2, tig = lane & 3;

    unsigned a_s = (unsigned)__cvta_generic_to_shared(asm0);
    unsigned w_s = (unsigned)__cvta_generic_to_shared(wsm0);

    if (t < 64) bias_sm[t] = bias[t];

    for (int i = t; i < 2048; i += 256) {      // 128 n x 16 c4
        int n = i >> 4, c4 = i & 15;
        float4 v = __ldg((const float4*)(fT + ((size_t)b * NP + n0 + n) * CC + c4 * 4));
        __half2 h0 = __floats2half2_rn(v.x, v.y);
        __half2 h1 = __floats2half2_rn(v.z, v.w);
        uint2 uu;
        uu.x = *(unsigned*)&h0;
        uu.y = *(unsigned*)&h1;
        *(uint2*)(asm0 + n * 36 + c4 * 2) = uu;
    }
    for (int i = t; i < 2048; i += 256) {      // 64 co x 32 k2
        int co = i >> 5, k2 = i & 31;
        float lo = __ldg(w + (size_t)(2 * k2) * 64 + co);
        float hi = __ldg(w + (size_t)(2 * k2 + 1) * 64 + co);
        __half2 h = __floats2half2_rn(lo, hi);
        wsm0[co * 36 + k2] = *(unsigned*)&h;
    }
    __syncthreads();

    float acc[2][4][4];
#pragma unroll
    for (int mt = 0; mt < 2; mt++)
#pragma unroll
        for (int nt = 0; nt < 4; nt++)
#pragma unroll
            for (int e = 0; e < 4; e++) acc[mt][nt][e] = 0.0f;

    unsigned a_base = a_s + (unsigned)((wy * 32 + gid) * 36 + tig) * 4;
    unsigned b_base = w_s + (unsigned)((wn * 32 + gid) * 36 + tig) * 4;
#pragma unroll
    for (int ks = 0; ks < 4; ks++) {
        unsigned ab = a_base + ks * 32;
        unsigned bb = b_base + ks * 32;
        unsigned a0, a1, a2, a3, a4, a5, a6, a7;
        LDS32(a0, ab);            LDS32(a1, ab + 1152);
        LDS32(a2, ab + 16);       LDS32(a3, ab + 1168);
        LDS32(a4, ab + 2304);     LDS32(a5, ab + 3456);
        LDS32(a6, ab + 2320);     LDS32(a7, ab + 3472);
        unsigned b0[4], b1[4];
#pragma unroll
        for (int nt = 0; nt < 4; nt++) {
            LDS32(b0[nt], bb + nt * 1152);
            LDS32(b1[nt], bb + nt * 1152 + 16);
        }
#pragma unroll
        for (int nt = 0; nt < 4; nt++) {
            MMA_F16(acc[0][nt], a0, a1, a2, a3, b0[nt], b1[nt]);
            MMA_F16(acc[1][nt], a4, a5, a6, a7, b0[nt], b1[nt]);
        }
    }
    __syncthreads();

#pragma unroll
    for (int mt = 0; mt < 2; mt++)
#pragma unroll
        for (int nt = 0; nt < 4; nt++) {
            int spat0 = wy * 32 + mt * 16 + gid;
            int cout0 = wn * 32 + nt * 8 + tig * 2;
            *(float2*)(res + spat0 * RES_PITCH + cout0) =
                make_float2(acc[mt][nt][0], acc[mt][nt][1]);
            *(float2*)(res + (spat0 + 8) * RES_PITCH + cout0) =
                make_float2(acc[mt][nt][2], acc[mt][nt][3]);
        }
    __syncthreads();

    {
        int s_ = t >> 1, h = t & 1;
        float* op = pT + ((size_t)b * NP + n0 + s_) * CC + h * 32;
        const float* rp = res + s_ * RES_PITCH + h * 32;
#pragma unroll
        for (int k = 0; k < 8; k++) {
            float4 v;
            v.x = rp[4 * k + 0] + bias_sm[h * 32 + 4 * k + 0];
            v.y = rp[4 * k + 1] + bias_sm[h * 32 + 4 * k + 1];
            v.z = rp[4 * k + 2] + bias_sm[h * 32 + 4 * k + 2];
            v.w = rp[4 * k + 3] + bias_sm[h * 32 + 4 * k + 3];
            *(float4*)(op + 4 * k) = v;
        }
    }
#pragma unroll
    for (int j = 0; j < 8; j++) {
        int c = wid * 8 + j;
        float bval = bias_sm[c];
        float s = 0, q = 0;
#pragma unroll
        for (int sy = 0; sy < 4; sy++) {
            float v = res[(sy * 32 + lane) * RES_PITCH + c] + bval;
            s += v; q += v * v;
        }
#pragma unroll
        for (int o = 16; o > 0; o >>= 1) {
            s += __shfl_xor_sync(0xffffffff, s, o);
            q += __shfl_xor_sync(0xffffffff, q, o);
        }
        if (lane == 0) { atomicAdd(&gsum[c], s); atomicAdd(&gsumsq[c], q); }
    }
}

// ---------------- final: devox(BN2+lrelu on the fly) + BN(p)+lrelu + add ----
__global__ void final_k(const float* __restrict__ vT, const float* __restrict__ pT,
                        const float* __restrict__ normc,
                        const float* __restrict__ sc2, const float* __restrict__ sh2,
                        const float* __restrict__ scp, const float* __restrict__ shp,
                        float* __restrict__ out) {
    __shared__ float res[64][65];
    __shared__ int cidx[64][8];
    __shared__ float cw[64][8];
    int b = blockIdx.y;
    int n0 = blockIdx.x * 64;
    int t = threadIdx.x;

    if (t < 64) {
        int n = n0 + t;
        float xs = normc[(b * 3 + 0) * NP + n];
        float ys = normc[(b * 3 + 1) * NP + n];
        float zs = normc[(b * 3 + 2) * NP + n];
        float x0f = floorf(xs), y0f = floorf(ys), z0f = floorf(zs);
        float fx = xs - x0f, fy = ys - y0f, fz = zs - z0f;
        int x0 = (int)x0f, y0 = (int)y0f, z0 = (int)z0f;
        int x1 = min(x0 + 1, 31), y1 = min(y0 + 1, 31), z1 = min(z0 + 1, 31);
#pragma unroll
        for (int k = 0; k < 8; k++) {
            int dx = (k >> 2) & 1, dy = (k >> 1) & 1, dz = k & 1;
            float wt = (dx ? fx : 1.0f - fx) * (dy ? fy : 1.0f - fy) * (dz ? fz : 1.0f - fz);
            int idx = ((dx ? x1 : x0) * 32 + (dy ? y1 : y0)) * 32 + (dz ? z1 : z0);
            cidx[t][k] = idx;
            cw[t][k] = wt;
        }
    }
    __syncthreads();

    int c = t & 63, ty = t >> 6;
    float sc2v = sc2[c], sh2v = sh2[c];
    float scpv = scp[c], shpv = shp[c];

    for (int j = ty; j < 64; j += 8) {
        int j2 = j + 4;
        float acc0 = 0.0f, acc1 = 0.0f;
#pragma unroll
        for (int k = 0; k < 8; k++) {
            float g0 = vT[((size_t)b * NV + cidx[j][k]) * CC + c];
            float g1 = vT[((size_t)b * NV + cidx[j2][k]) * CC + c];
            float u0 = fmaf(g0, sc2v, sh2v);
            float u1 = fmaf(g1, sc2v, sh2v);
            u0 = u0 >= 0 ? u0 : ALPHA * u0;
            u1 = u1 >= 0 ? u1 : ALPHA * u1;
            acc0 += cw[j][k] * u0;
            acc1 += cw[j2][k] * u1;
        }
        float pv0 = fmaf(pT[((size_t)b * NP + n0 + j) * CC + c], scpv, shpv);
        float pv1 = fmaf(pT[((size_t)b * NP + n0 + j2) * CC + c], scpv, shpv);
        pv0 = pv0 >= 0 ? pv0 : ALPHA * pv0;
        pv1 = pv1 >= 0 ? pv1 : ALPHA * pv1;
        res[c][j] = acc0 + pv0;
        res[c][j2] = acc1 + pv1;
    }
    __syncthreads();

    for (int i = t; i < 4096; i += 256) {
        int c2 = i >> 6, j = i & 63;
        out[((size_t)b * CC + c2) * NP + n0 + j] = res[c2][j];
    }
}

// ---------------- launcher ----------------
extern "C" void kernel_launch(void* const* d_in, const int* in_sizes, int n_in,
                              void* d_out, int out_size) {
    const float* feat   = (const float*)d_in[0];
    const float* coords = (const float*)d_in[1];
    const float* c1w    = (const float*)d_in[2];
    const float* c1b    = (const float*)d_in[3];
    const float* g1     = (const float*)d_in[4];
    const float* b1     = (const float*)d_in[5];
    const float* c2w    = (const float*)d_in[6];
    const float* c2b    = (const float*)d_in[7];
    const float* g2     = (const float*)d_in[8];
    const float* b2     = (const float*)d_in[9];
    const float* pw     = (const float*)d_in[10];
    const float* pb     = (const float*)d_in[11];
    const float* pg     = (const float*)d_in[12];
    const float* pbeta  = (const float*)d_in[13];
    float* out = (float*)d_out;

    float *fT, *tmp, *cnt, *bufB, *pT, *normc, *cmean, *stats, *scsh;
    unsigned* cmaxb;
    cudaGetSymbolAddress((void**)&fT, g_fT);
    cudaGetSymbolAddress((void**)&tmp, g_tmp);
    cudaGetSymbolAddress((void**)&cnt, g_cnt);
    cudaGetSymbolAddress((void**)&bufB, g_bufB);
    cudaGetSymbolAddress((void**)&pT, g_pT);
    cudaGetSymbolAddress((void**)&normc, g_normc);
    cudaGetSymbolAddress((void**)&cmean, g_cmean);
    cudaGetSymbolAddress((void**)&cmaxb, g_cmaxb);
    cudaGetSymbolAddress((void**)&stats, g_stats);
    cudaGetSymbolAddress((void**)&scsh, g_scsh);

    float* sum1 = stats + 0 * CC;  float* sq1 = stats + 1 * CC;
    float* sum2 = stats + 2 * CC;  float* sq2 = stats + 3 * CC;
    float* psum = stats + 4 * CC;  float* psq = stats + 5 * CC;
    float* sc1 = scsh + 0 * CC;    float* sh1 = scsh + 1 * CC;
    float* sc2 = scsh + 2 * CC;    float* sh2 = scsh + 3 * CC;
    float* scp = scsh + 4 * CC;    float* shp = scsh + 5 * CC;

    cudaFuncSetAttribute(conv3d_mma<0>, cudaFuncAttributeMaxDynamicSharedMemorySize, CONV_DYN);
    cudaFuncSetAttribute(conv3d_mma<2>, cudaFuncAttributeMaxDynamicSharedMemorySize, CONV_DYN);
    cudaFuncSetAttribute(pgemm_mma, cudaFuncAttributeMaxDynamicSharedMemorySize, PG_DYN);

    const float invV = 1.0f / (float)(BB * NV);
    const float invP = 1.0f / (float)(BB * NP);

    // voxelize
    zero_all<<<4096, 256>>>(tmp, cnt, stats, cmean, cmaxb);
    transpose_feat<<<dim3(NP / 32, BB), 256>>>(feat, fT);
    coord_mean_p<<<dim3(32, BB), 256>>>(coords, cmean);
    coord_max_p<<<dim3(32, BB), 256>>>(coords, cmean, cmaxb);
    scatter<<<BB * NP / 16, 256>>>(coords, fT, cmean, cmaxb, normc, tmp, cnt);

    // conv1: voxel sums+counts in (finalize fused), channels-last out
    conv3d_mma<0><<<dim3(8, 32, BB), 256, CONV_DYN>>>(tmp, cnt, bufB, c1w, c1b,
                                                      nullptr, nullptr, sum1, sq1);
    mkscale<<<1, 64>>>(sum1, sq1, g1, b1, invV, sc1, sh1);

    // conv2: channels-last in with BN1+lrelu fused, channels-last out into tmp
    conv3d_mma<2><<<dim3(8, 32, BB), 256, CONV_DYN>>>(bufB, nullptr, tmp, c2w, c2b,
                                                      sc1, sh1, sum2, sq2);
    mkscale<<<1, 64>>>(sum2, sq2, g2, b2, invV, sc2, sh2);

    // point branch: fp16 tensor-core GEMM + fused stats
    pgemm_mma<<<dim3(NP / 128, BB), 256, PG_DYN>>>(fT, pw, pb, pT, psum, psq);
    mkscale<<<1, 64>>>(psum, psq, pg, pbeta, invP, scp, shp);

    // devoxelize (BN2+lrelu applied on gather) + point BN + add
    final_k<<<dim3(NP / 64, BB), 256>>>(tmp, pT, normc, sc2, sh2, scp, shp, out);

    // coords passthrough (second tuple output), if the harness expects it
    int main_sz = BB * CC * NP;
    int coord_sz = BB * 3 * NP;
    if (out_size >= main_sz + coord_sz)
        copy_kernel<<<coord_sz / 256, 256>>>(coords, out + main_sz, coord_sz);
}

// round 17
// speedup vs baseline: 1.0857x; 1.0572x over previous
#include <cuda_runtime.h>
#include <cuda_fp16.h>

#define BB 8
#define CC 64
#define NP 16384
#define RR 32
#define NV 32768          // 32^3
#define ALPHA 0.1f
#define BNEPS 1e-4f
#define VOXEPS 1e-6f

// ---------------- scratch (device globals; no allocation allowed) ----------
__device__ float g_fT[BB * NP * CC];        // features transposed [b][n][c]
__device__ float g_tmp[BB * NV * CC];       // voxel sums [b][v][c]; later raw conv2 out
__device__ float g_cnt[BB * NV];            // voxel counts
__device__ float g_bufB[BB * CC * NV];      // conv1 output (channels-last [b][v][c])
__device__ float g_pT[BB * NP * CC];        // point branch [b][n][c]
__device__ float g_normc[BB * 3 * NP];      // normalized coords in [0,31]
__device__ float g_cmean[BB * 3];           // coordinate SUMS
__device__ unsigned g_cmaxb[BB];            // max dist^2 as float bits
__device__ float g_stats[6 * CC];           // sum1,sq1,sum2,sq2,psum,psq
__device__ float g_scsh[6 * CC];            // sc1,sh1,sc2,sh2,scp,shp
__device__ unsigned g_wh1[2 * 27 * 64 * 16];  // conv1 W as half2, [cig][koff][co][k2]
__device__ unsigned g_wh2[2 * 27 * 64 * 16];  // conv2 W as half2

// ---------------- utility kernels ----------------
// zero tmp + cnt + stats + cmean + cmaxb in ONE launch
__global__ void zero_all(float* tmp, float* cnt, float* stats, float* cmean,
                         unsigned* cmaxb) {
    size_t i = (size_t)blockIdx.x * blockDim.x + threadIdx.x;
    size_t stride = (size_t)gridDim.x * blockDim.x;
    const size_t ntmp = (size_t)BB * NV * CC;
    for (size_t k = i; k < ntmp; k += stride) tmp[k] = 0.0f;
    for (size_t k = i; k < (size_t)BB * NV; k += stride) cnt[k] = 0.0f;
    if (i < 6 * CC) stats[i] = 0.0f;
    if (i < BB * 3) cmean[i] = 0.0f;
    if (i < BB) cmaxb[i] = 0u;
}

// pre-convert conv weights to half2 in smem-matched layout [cig][koff][co][k2]
__global__ void wprep(const float* __restrict__ w, unsigned* __restrict__ wh) {
    int i = blockIdx.x * 256 + threadIdx.x;     // 55296 total
    int k2 = i & 15, co = (i >> 4) & 63;
    int rest = i >> 10;
    int koff = rest % 27, cig = rest / 27;
    int ci = cig * 32 + 2 * k2;
    float lo = w[((size_t)(koff * 64 + ci)) * 64 + co];
    float hi = w[((size_t)(koff * 64 + ci + 1)) * 64 + co];
    __half2 h = __floats2half2_rn(lo, hi);
    wh[i] = *(unsigned*)&h;
}

__global__ void copy_kernel(const float* __restrict__ src, float* __restrict__ dst, int n) {
    int i = blockIdx.x * blockDim.x + threadIdx.x;
    int stride = gridDim.x * blockDim.x;
    for (; i < n; i += stride) dst[i] = src[i];
}

__global__ void mkscale(const float* __restrict__ sum, const float* __restrict__ sumsq,
                        const float* __restrict__ gamma, const float* __restrict__ beta,
                        float invcnt, float* __restrict__ sc, float* __restrict__ sh) {
    int c = threadIdx.x;
    float mean = sum[c] * invcnt;
    float var = sumsq[c] * invcnt - mean * mean;
    float s = gamma[c] * rsqrtf(var + BNEPS);
    sc[c] = s;
    sh[c] = beta[c] - mean * s;
}

// ---------------- features transpose [b][c][n] -> [b][n][c] ----------------
__global__ void transpose_feat(const float* __restrict__ feat, float* __restrict__ fT) {
    __shared__ float s[CC][33];
    int b = blockIdx.y;
    int n0 = blockIdx.x * 32;
    int t = threadIdx.x;
    for (int i = t; i < 32 * 64; i += 256) {
        int c = i >> 5, n = i & 31;
        s[c][n] = feat[(b * CC + c) * NP + n0 + n];
    }
    __syncthreads();
    for (int i = t; i < 32 * 64; i += 256) {
        int n = i >> 6, c = i & 63;
        fT[((size_t)b * NP + n0 + n) * CC + c] = s[c][n];
    }
}

// ---------------- coord statistics ----------------
__global__ void coord_mean_p(const float* __restrict__ coords, float* __restrict__ cmean) {
    int b = blockIdx.y;
    int n0 = blockIdx.x * 512;
    int t = threadIdx.x;
    float s0 = 0, s1 = 0, s2 = 0;
    for (int n = n0 + t; n < n0 + 512; n += 256) {
        s0 += coords[(b * 3 + 0) * NP + n];
        s1 += coords[(b * 3 + 1) * NP + n];
        s2 += coords[(b * 3 + 2) * NP + n];
    }
#pragma unroll
    for (int o = 16; o > 0; o >>= 1) {
        s0 += __shfl_xor_sync(0xffffffff, s0, o);
        s1 += __shfl_xor_sync(0xffffffff, s1, o);
        s2 += __shfl_xor_sync(0xffffffff, s2, o);
    }
    if ((t & 31) == 0) {
        atomicAdd(&cmean[b * 3 + 0], s0);
        atomicAdd(&cmean[b * 3 + 1], s1);
        atomicAdd(&cmean[b * 3 + 2], s2);
    }
}

__global__ void coord_max_p(const float* __restrict__ coords, const float* __restrict__ cmean,
                            unsigned* __restrict__ cmaxb) {
    int b = blockIdx.y;
    int n0 = blockIdx.x * 512;
    int t = threadIdx.x;
    float invn = 1.0f / (float)NP;
    float mx = cmean[b * 3 + 0] * invn, my = cmean[b * 3 + 1] * invn, mz = cmean[b * 3 + 2] * invn;
    float m = 0.0f;
    for (int n = n0 + t; n < n0 + 512; n += 256) {
        float dx = coords[(b * 3 + 0) * NP + n] - mx;
        float dy = coords[(b * 3 + 1) * NP + n] - my;
        float dz = coords[(b * 3 + 2) * NP + n] - mz;
        m = fmaxf(m, dx * dx + dy * dy + dz * dz);
    }
#pragma unroll
    for (int o = 16; o > 0; o >>= 1) m = fmaxf(m, __shfl_xor_sync(0xffffffff, m, o));
    if ((t & 31) == 0) atomicMax(&cmaxb[b], __float_as_uint(m));
}

// ---------------- voxelize scatter (red.v4: 16 threads/point, 4 ch each) ---
__global__ void scatter(const float* __restrict__ coords, const float* __restrict__ fT,
                        const float* __restrict__ cmean, const unsigned* __restrict__ cmaxb,
                        float* __restrict__ normc, float* __restrict__ tmp,
                        float* __restrict__ cnt) {
    int t = threadIdx.x;
    int pi = blockIdx.x * 16 + (t >> 4);
    int j = t & 15;
    int b = pi / NP;
    int n = pi - b * NP;

    float invn = 1.0f / (float)NP;
    float r = sqrtf(__uint_as_float(cmaxb[b]));
    float inv = 1.0f / (2.0f * r + VOXEPS);
    float nx = (coords[(b * 3 + 0) * NP + n] - cmean[b * 3 + 0] * invn) * inv + 0.5f;
    float ny = (coords[(b * 3 + 1) * NP + n] - cmean[b * 3 + 1] * invn) * inv + 0.5f;
    float nz = (coords[(b * 3 + 2) * NP + n] - cmean[b * 3 + 2] * invn) * inv + 0.5f;
    nx = fminf(fmaxf(nx * (float)RR, 0.0f), (float)(RR - 1));
    ny = fminf(fmaxf(ny * (float)RR, 0.0f), (float)(RR - 1));
    nz = fminf(fmaxf(nz * (float)RR, 0.0f), (float)(RR - 1));
    int vx = __float2int_rn(nx), vy = __float2int_rn(ny), vz = __float2int_rn(nz);
    int v = (vx * RR + vy) * RR + vz;

    float4 f = *(const float4*)(fT + ((size_t)b * NP + n) * CC + j * 4);
    float* dst = tmp + ((size_t)b * NV + v) * CC + j * 4;
    asm volatile("red.global.add.v4.f32 [%0], {%1,%2,%3,%4};"
                 :: "l"(dst), "f"(f.x), "f"(f.y), "f"(f.z), "f"(f.w) : "memory");
    if (j == 0) atomicAdd(&cnt[b * NV + v], 1.0f);
    if (j < 3) normc[(b * 3 + j) * NP + n] = (j == 0 ? nx : (j == 1 ? ny : nz));
}

// ================= fp16 mma.sync conv (cp.async weight staging) ============
#define LDS32(dst, addr) asm volatile("ld.shared.b32 %0, [%1];" : "=r"(dst) : "r"(addr))
#define MMA_F16(d, a0, a1, a2, a3, b0, b1)                                    \
    asm volatile(                                                             \
        "mma.sync.aligned.m16n8k16.row.col.f32.f16.f16.f32 "                  \
        "{%0,%1,%2,%3}, {%4,%5,%6,%7}, {%8,%9}, {%0,%1,%2,%3};"               \
        : "+f"(d[0]), "+f"(d[1]), "+f"(d[2]), "+f"(d[3])                      \
        : "r"(a0), "r"(a1), "r"(a2), "r"(a3), "r"(b0), "r"(b1))

#define CWF 1280          // W' u32 per buffer: 64 n-rows x 20
#define CSLAB 12240       // slab u32: 612 rows x 20
#define RES_PITCH 68
#define CONV_DYN ((2 * CWF + CSLAB) * 4)   // 59200 B

template <int INMODE>
__global__ __launch_bounds__(256, 3)
void conv3d_mma(const float* __restrict__ in, const float* __restrict__ cnt,
                float* __restrict__ out,
                const unsigned* __restrict__ wh, const float* __restrict__ bias,
                const float* __restrict__ insc, const float* __restrict__ insh,
                float* __restrict__ gsum, float* __restrict__ gsumsq) {
    extern __shared__ __align__(16) float dsm[];
    __shared__ float sc_sm[64], sh_sm[64], bias_sm[64];

    unsigned* slab = (unsigned*)dsm + 2 * CWF;
    float* res = (float*)slab;  // reused after compute (128 x 68 <= 12240)

    int b = blockIdx.z, z0 = blockIdx.y, y0 = blockIdx.x * 4;
    int t = threadIdx.x, lane = t & 31, wid = t >> 5;
    int wy = wid >> 1, wn = wid & 1;
    int gid = lane >> 2, tig = lane & 3;

    unsigned smem_u = (unsigned)__cvta_generic_to_shared(dsm);
    unsigned wsm_s[2] = {smem_u, smem_u + CWF * 4};
    unsigned slab_s = smem_u + 2 * CWF * 4;

    if (t < 64) {
        bias_sm[t] = bias[t];
        if (INMODE == 2) { sc_sm[t] = insc[t]; sh_sm[t] = insh[t]; }
    }
    __syncthreads();

    float acc[2][4][4];
#pragma unroll
    for (int mt = 0; mt < 2; mt++)
#pragma unroll
        for (int nt = 0; nt < 4; nt++)
#pragma unroll
            for (int e = 0; e < 4; e++) acc[mt][nt][e] = 0.0f;

    // slab: row r = (zs*6+ys)*34+xs, 16 half2 (32 ci) per row, pitch 20 u32
    auto load_slab = [&](int cig) {
        for (int i = t; i < 4896; i += 256) {
            int zy = i / 272, r = i - zy * 272;
            int c4 = r / 34, xs = r - c4 * 34;
            int zs = zy / 6, ys = zy - zs * 6;
            int zg = z0 - 1 + zs, yg = y0 - 1 + ys, xg = xs - 1;
            bool ok = (unsigned)zg < 32u && (unsigned)yg < 32u && (unsigned)xg < 32u;
            int vox = zg * 1024 + yg * 32 + xg;
            float4 v;
            if (INMODE == 0) {
                float4 sums = ok ? __ldg((const float4*)(in + ((size_t)b * NV + vox) * CC
                                                          + cig * 32 + c4 * 4))
                                 : make_float4(0.f, 0.f, 0.f, 0.f);
                float inv = ok ? 1.0f / fmaxf(__ldg(cnt + (size_t)b * NV + vox), 1.0f) : 0.0f;
                v.x = sums.x * inv; v.y = sums.y * inv;
                v.z = sums.z * inv; v.w = sums.w * inv;
            } else {
                v = ok ? __ldg((const float4*)(in + ((size_t)b * NV + vox) * CC
                                                + cig * 32 + c4 * 4))
                       : make_float4(0.f, 0.f, 0.f, 0.f);
                int c = cig * 32 + c4 * 4;
                float u;
                u = fmaf(v.x, sc_sm[c + 0], sh_sm[c + 0]); v.x = u >= 0 ? u : ALPHA * u;
                u = fmaf(v.y, sc_sm[c + 1], sh_sm[c + 1]); v.y = u >= 0 ? u : ALPHA * u;
                u = fmaf(v.z, sc_sm[c + 2], sh_sm[c + 2]); v.z = u >= 0 ? u : ALPHA * u;
                u = fmaf(v.w, sc_sm[c + 3], sh_sm[c + 3]); v.w = u >= 0 ? u : ALPHA * u;
                if (!ok) v = make_float4(0.f, 0.f, 0.f, 0.f);  // pad AFTER transform
            }
            __half2 h0 = __floats2half2_rn(v.x, v.y);
            __half2 h1 = __floats2half2_rn(v.z, v.w);
            uint2 uu;
            uu.x = *(unsigned*)&h0;
            uu.y = *(unsigned*)&h1;
            int row = (zs * 6 + ys) * 34 + xs;
            *(uint2*)(slab + row * 20 + c4 * 2) = uu;
        }
    };

    // async weight staging: 1x cp.async 16B per thread per koff
    int stg_co = t >> 2, stg_j = t & 3;
    auto w_stage = [&](int cig, int koff, unsigned dst_base) {
        unsigned dst = dst_base + (unsigned)(stg_co * 20 + 4 * stg_j) * 4;
        const unsigned* src = wh + ((size_t)(cig * 27 + koff) * 64 + stg_co) * 16 + 4 * stg_j;
        asm volatile("cp.async.ca.shared.global [%0], [%1], 16;"
                     :: "r"(dst), "l"(src) : "memory");
        asm volatile("cp.async.commit_group;" ::: "memory");
    };

    auto compute = [&](int buf, int koff) {
        int dz = koff / 9, rem = koff - dz * 9;
        int dy = rem / 3, dx = rem - dy * 3;
        unsigned a_base = slab_s +
            (unsigned)((((dz * 6 + wy + dy) * 34) + gid + dx) * 20 + tig) * 4;
        unsigned b_base = wsm_s[buf] + (unsigned)((wn * 32 + gid) * 20 + tig) * 4;
#pragma unroll
        for (int ks = 0; ks < 2; ks++) {
            unsigned ab = a_base + ks * 32;
            unsigned bb = b_base + ks * 32;
            unsigned a0, a1, a2, a3, a4, a5, a6, a7;
            LDS32(a0, ab);            LDS32(a1, ab + 640);
            LDS32(a2, ab + 16);       LDS32(a3, ab + 656);
            LDS32(a4, ab + 1280);     LDS32(a5, ab + 1920);
            LDS32(a6, ab + 1296);     LDS32(a7, ab + 1936);
            unsigned b0[4], b1[4];
#pragma unroll
            for (int nt = 0; nt < 4; nt++) {
                LDS32(b0[nt], bb + nt * 640);
                LDS32(b1[nt], bb + nt * 640 + 16);
            }
#pragma unroll
            for (int nt = 0; nt < 4; nt++) {
                MMA_F16(acc[0][nt], a0, a1, a2, a3, b0[nt], b1[nt]);
                MMA_F16(acc[1][nt], a4, a5, a6, a7, b0[nt], b1[nt]);
            }
        }
    };

#pragma unroll 1
    for (int cig = 0; cig < 2; cig++) {
        w_stage(cig, 0, wsm_s[0]);     // async; overlaps slab load
        load_slab(cig);
        asm volatile("cp.async.wait_group 0;" ::: "memory");
        __syncthreads();
#pragma unroll 1
        for (int koff = 0; koff < 27; koff++) {
            if (koff < 26) w_stage(cig, koff + 1, wsm_s[(koff + 1) & 1]);  // async issue first
            compute(koff & 1, koff);
            if (koff < 26) {
                asm volatile("cp.async.wait_group 0;" ::: "memory");
                __syncthreads();
            }
        }
        __syncthreads();   // protect slab (cig flip) / res reuse
    }

    // ---- epilogue ----
#pragma unroll
    for (int mt = 0; mt < 2; mt++)
#pragma unroll
        for (int nt = 0; nt < 4; nt++) {
            int spat0 = wy * 32 + mt * 16 + gid;
            int cout0 = wn * 32 + nt * 8 + tig * 2;
            *(float2*)(res + spat0 * RES_PITCH + cout0) =
                make_float2(acc[mt][nt][0], acc[mt][nt][1]);
            *(float2*)(res + (spat0 + 8) * RES_PITCH + cout0) =
                make_float2(acc[mt][nt][2], acc[mt][nt][3]);
        }
    __syncthreads();

    {
        int s_ = t >> 1, h = t & 1;
        int vox = z0 * 1024 + (y0 + (s_ >> 5)) * 32 + (s_ & 31);
        float* op = out + ((size_t)b * NV + vox) * CC + h * 32;
        const float* rp = res + s_ * RES_PITCH + h * 32;
#pragma unroll
        for (int k = 0; k < 8; k++) {
            float4 v;
            v.x = rp[4 * k + 0] + bias_sm[h * 32 + 4 * k + 0];
            v.y = rp[4 * k + 1] + bias_sm[h * 32 + 4 * k + 1];
            v.z = rp[4 * k + 2] + bias_sm[h * 32 + 4 * k + 2];
            v.w = rp[4 * k + 3] + bias_sm[h * 32 + 4 * k + 3];
            *(float4*)(op + 4 * k) = v;
        }
    }
#pragma unroll
    for (int j = 0; j < 8; j++) {
        int c = wid * 8 + j;
        float bval = bias_sm[c];
        float s = 0, q = 0;
#pragma unroll
        for (int sy = 0; sy < 4; sy++) {
            float v = res[(sy * 32 + lane) * RES_PITCH + c] + bval;
            s += v; q += v * v;
        }
#pragma unroll
        for (int o = 16; o > 0; o >>= 1) {
            s += __shfl_xor_sync(0xffffffff, s, o);
            q += __shfl_xor_sync(0xffffffff, q, o);
        }
        if (lane == 0) { atomicAdd(&gsum[c], s); atomicAdd(&gsumsq[c], q); }
    }
}

// ================= fp16 mma.sync point GEMM + fused stats ===================
#define PGA_U32 (128 * 36)   // 4608
#define PGW_U32 (64 * 36)    // 2304
#define PG_DYN ((PGA_U32 + PGW_U32) * 4 + 128 * RES_PITCH * 4)  // 62464 B

__global__ __launch_bounds__(256, 2)
void pgemm_mma(const float* __restrict__ fT, const float* __restrict__ w,
               const float* __restrict__ bias, float* __restrict__ pT,
               float* __restrict__ gsum, float* __restrict__ gsumsq) {
    extern __shared__ __align__(16) float dsm[];
    __shared__ float bias_sm[64];
    unsigned* asm0 = (unsigned*)dsm;            // [128][36]
    unsigned* wsm0 = (unsigned*)dsm + PGA_U32;  // [64][36]
    float* res = dsm;                           // reuse after compute

    int b = blockIdx.y;
    int n0 = blockIdx.x * 128;
    int t = threadIdx.x, lane = t & 31, wid = t >> 5;
    int wy = wid >> 1, wn = wid & 1;
    int gid = lane >> 2, tig = lane & 3;

    unsigned a_s = (unsigned)__cvta_generic_to_shared(asm0);
    unsigned w_s = (unsigned)__cvta_generic_to_shared(wsm0);

    if (t < 64) bias_sm[t] = bias[t];

    for (int i = t; i < 2048; i += 256) {      // 128 n x 16 c4
        int n = i >> 4, c4 = i & 15;
        float4 v = __ldg((const float4*)(fT + ((size_t)b * NP + n0 + n) * CC + c4 * 4));
        __half2 h0 = __floats2half2_rn(v.x, v.y);
        __half2 h1 = __floats2half2_rn(v.z, v.w);
        uint2 uu;
        uu.x = *(unsigned*)&h0;
        uu.y = *(unsigned*)&h1;
        *(uint2*)(asm0 + n * 36 + c4 * 2) = uu;
    }
    for (int i = t; i < 2048; i += 256) {      // 64 co x 32 k2
        int co = i >> 5, k2 = i & 31;
        float lo = __ldg(w + (size_t)(2 * k2) * 64 + co);
        float hi = __ldg(w + (size_t)(2 * k2 + 1) * 64 + co);
        __half2 h = __floats2half2_rn(lo, hi);
        wsm0[co * 36 + k2] = *(unsigned*)&h;
    }
    __syncthreads();

    float acc[2][4][4];
#pragma unroll
    for (int mt = 0; mt < 2; mt++)
#pragma unroll
        for (int nt = 0; nt < 4; nt++)
#pragma unroll
            for (int e = 0; e < 4; e++) acc[mt][nt][e] = 0.0f;

    unsigned a_base = a_s + (unsigned)((wy * 32 + gid) * 36 + tig) * 4;
    unsigned b_base = w_s + (unsigned)((wn * 32 + gid) * 36 + tig) * 4;
#pragma unroll
    for (int ks = 0; ks < 4; ks++) {
        unsigned ab = a_base + ks * 32;
        unsigned bb = b_base + ks * 32;
        unsigned a0, a1, a2, a3, a4, a5, a6, a7;
        LDS32(a0, ab);            LDS32(a1, ab + 1152);
        LDS32(a2, ab + 16);       LDS32(a3, ab + 1168);
        LDS32(a4, ab + 2304);     LDS32(a5, ab + 3456);
        LDS32(a6, ab + 2320);     LDS32(a7, ab + 3472);
        unsigned b0[4], b1[4];
#pragma unroll
        for (int nt = 0; nt < 4; nt++) {
            LDS32(b0[nt], bb + nt * 1152);
            LDS32(b1[nt], bb + nt * 1152 + 16);
        }
#pragma unroll
        for (int nt = 0; nt < 4; nt++) {
            MMA_F16(acc[0][nt], a0, a1, a2, a3, b0[nt], b1[nt]);
            MMA_F16(acc[1][nt], a4, a5, a6, a7, b0[nt], b1[nt]);
        }
    }
    __syncthreads();

#pragma unroll
    for (int mt = 0; mt < 2; mt++)
#pragma unroll
        for (int nt = 0; nt < 4; nt++) {
            int spat0 = wy * 32 + mt * 16 + gid;
            int cout0 = wn * 32 + nt * 8 + tig * 2;
            *(float2*)(res + spat0 * RES_PITCH + cout0) =
                make_float2(acc[mt][nt][0], acc[mt][nt][1]);
            *(float2*)(res + (spat0 + 8) * RES_PITCH + cout0) =
                make_float2(acc[mt][nt][2], acc[mt][nt][3]);
        }
    __syncthreads();

    {
        int s_ = t >> 1, h = t & 1;
        float* op = pT + ((size_t)b * NP + n0 + s_) * CC + h * 32;
        const float* rp = res + s_ * RES_PITCH + h * 32;
#pragma unroll
        for (int k = 0; k < 8; k++) {
            float4 v;
            v.x = rp[4 * k + 0] + bias_sm[h * 32 + 4 * k + 0];
            v.y = rp[4 * k + 1] + bias_sm[h * 32 + 4 * k + 1];
            v.z = rp[4 * k + 2] + bias_sm[h * 32 + 4 * k + 2];
            v.w = rp[4 * k + 3] + bias_sm[h * 32 + 4 * k + 3];
            *(float4*)(op + 4 * k) = v;
        }
    }
#pragma unroll
    for (int j = 0; j < 8; j++) {
        int c = wid * 8 + j;
        float bval = bias_sm[c];
        float s = 0, q = 0;
#pragma unroll
        for (int sy = 0; sy < 4; sy++) {
            float v = res[(sy * 32 + lane) * RES_PITCH + c] + bval;
            s += v; q += v * v;
        }
#pragma unroll
        for (int o = 16; o > 0; o >>= 1) {
            s += __shfl_xor_sync(0xffffffff, s, o);
            q += __shfl_xor_sync(0xffffffff, q, o);
        }
        if (lane == 0) { atomicAdd(&gsum[c], s); atomicAdd(&gsumsq[c], q); }
    }
}

// ---------------- final: devox(BN2+lrelu on the fly) + BN(p)+lrelu + add ----
__global__ void final_k(const float* __restrict__ vT, const float* __restrict__ pT,
                        const float* __restrict__ normc,
                        const float* __restrict__ sc2, const float* __restrict__ sh2,
                        const float* __restrict__ scp, const float* __restrict__ shp,
                        float* __restrict__ out) {
    __shared__ float res[64][65];
    __shared__ int cidx[64][8];
    __shared__ float cw[64][8];
    int b = blockIdx.y;
    int n0 = blockIdx.x * 64;
    int t = threadIdx.x;

    if (t < 64) {
        int n = n0 + t;
        float xs = normc[(b * 3 + 0) * NP + n];
        float ys = normc[(b * 3 + 1) * NP + n];
        float zs = normc[(b * 3 + 2) * NP + n];
        float x0f = floorf(xs), y0f = floorf(ys), z0f = floorf(zs);
        float fx = xs - x0f, fy = ys - y0f, fz = zs - z0f;
        int x0 = (int)x0f, y0 = (int)y0f, z0 = (int)z0f;
        int x1 = min(x0 + 1, 31), y1 = min(y0 + 1, 31), z1 = min(z0 + 1, 31);
#pragma unroll
        for (int k = 0; k < 8; k++) {
            int dx = (k >> 2) & 1, dy = (k >> 1) & 1, dz = k & 1;
            float wt = (dx ? fx : 1.0f - fx) * (dy ? fy : 1.0f - fy) * (dz ? fz : 1.0f - fz);
            int idx = ((dx ? x1 : x0) * 32 + (dy ? y1 : y0)) * 32 + (dz ? z1 : z0);
            cidx[t][k] = idx;
            cw[t][k] = wt;
        }
    }
    __syncthreads();

    int c = t & 63, ty = t >> 6;
    float sc2v = sc2[c], sh2v = sh2[c];
    float scpv = scp[c], shpv = shp[c];

    for (int j = ty; j < 64; j += 8) {
        int j2 = j + 4;
        float acc0 = 0.0f, acc1 = 0.0f;
#pragma unroll
        for (int k = 0; k < 8; k++) {
            float g0 = vT[((size_t)b * NV + cidx[j][k]) * CC + c];
            float g1 = vT[((size_t)b * NV + cidx[j2][k]) * CC + c];
            float u0 = fmaf(g0, sc2v, sh2v);
            float u1 = fmaf(g1, sc2v, sh2v);
            u0 = u0 >= 0 ? u0 : ALPHA * u0;
            u1 = u1 >= 0 ? u1 : ALPHA * u1;
            acc0 += cw[j][k] * u0;
            acc1 += cw[j2][k] * u1;
        }
        float pv0 = fmaf(pT[((size_t)b * NP + n0 + j) * CC + c], scpv, shpv);
        float pv1 = fmaf(pT[((size_t)b * NP + n0 + j2) * CC + c], scpv, shpv);
        pv0 = pv0 >= 0 ? pv0 : ALPHA * pv0;
        pv1 = pv1 >= 0 ? pv1 : ALPHA * pv1;
        res[c][j] = acc0 + pv0;
        res[c][j2] = acc1 + pv1;
    }
    __syncthreads();

    for (int i = t; i < 4096; i += 256) {
        int c2 = i >> 6, j = i & 63;
        out[((size_t)b * CC + c2) * NP + n0 + j] = res[c2][j];
    }
}

// ---------------- launcher ----------------
extern "C" void kernel_launch(void* const* d_in, const int* in_sizes, int n_in,
                              void* d_out, int out_size) {
    const float* feat   = (const float*)d_in[0];
    const float* coords = (const float*)d_in[1];
    const float* c1w    = (const float*)d_in[2];
    const float* c1b    = (const float*)d_in[3];
    const float* g1     = (const float*)d_in[4];
    const float* b1     = (const float*)d_in[5];
    const float* c2w    = (const float*)d_in[6];
    const float* c2b    = (const float*)d_in[7];
    const float* g2     = (const float*)d_in[8];
    const float* b2     = (const float*)d_in[9];
    const float* pw     = (const float*)d_in[10];
    const float* pb     = (const float*)d_in[11];
    const float* pg     = (const float*)d_in[12];
    const float* pbeta  = (const float*)d_in[13];
    float* out = (float*)d_out;

    float *fT, *tmp, *cnt, *bufB, *pT, *normc, *cmean, *stats, *scsh;
    unsigned *cmaxb, *wh1, *wh2;
    cudaGetSymbolAddress((void**)&fT, g_fT);
    cudaGetSymbolAddress((void**)&tmp, g_tmp);
    cudaGetSymbolAddress((void**)&cnt, g_cnt);
    cudaGetSymbolAddress((void**)&bufB, g_bufB);
    cudaGetSymbolAddress((void**)&pT, g_pT);
    cudaGetSymbolAddress((void**)&normc, g_normc);
    cudaGetSymbolAddress((void**)&cmean, g_cmean);
    cudaGetSymbolAddress((void**)&cmaxb, g_cmaxb);
    cudaGetSymbolAddress((void**)&stats, g_stats);
    cudaGetSymbolAddress((void**)&scsh, g_scsh);
    cudaGetSymbolAddress((void**)&wh1, g_wh1);
    cudaGetSymbolAddress((void**)&wh2, g_wh2);

    float* sum1 = stats + 0 * CC;  float* sq1 = stats + 1 * CC;
    float* sum2 = stats + 2 * CC;  float* sq2 = stats + 3 * CC;
    float* psum = stats + 4 * CC;  float* psq = stats + 5 * CC;
    float* sc1 = scsh + 0 * CC;    float* sh1 = scsh + 1 * CC;
    float* sc2 = scsh + 2 * CC;    float* sh2 = scsh + 3 * CC;
    float* scp = scsh + 4 * CC;    float* shp = scsh + 5 * CC;

    cudaFuncSetAttribute(conv3d_mma<0>, cudaFuncAttributeMaxDynamicSharedMemorySize, CONV_DYN);
    cudaFuncSetAttribute(conv3d_mma<2>, cudaFuncAttributeMaxDynamicSharedMemorySize, CONV_DYN);
    cudaFuncSetAttribute(pgemm_mma, cudaFuncAttributeMaxDynamicSharedMemorySize, PG_DYN);

    const float invV = 1.0f / (float)(BB * NV);
    const float invP = 1.0f / (float)(BB * NP);

    // prep: zero scratch + pre-convert conv weights to fp16 (smem layout)
    zero_all<<<4096, 256>>>(tmp, cnt, stats, cmean, cmaxb);
    wprep<<<216, 256>>>(c1w, wh1);
    wprep<<<216, 256>>>(c2w, wh2);
    transpose_feat<<<dim3(NP / 32, BB), 256>>>(feat, fT);
    coord_mean_p<<<dim3(32, BB), 256>>>(coords, cmean);
    coord_max_p<<<dim3(32, BB), 256>>>(coords, cmean, cmaxb);
    scatter<<<BB * NP / 16, 256>>>(coords, fT, cmean, cmaxb, normc, tmp, cnt);

    // conv1: voxel sums+counts in (finalize fused), channels-last out
    conv3d_mma<0><<<dim3(8, 32, BB), 256, CONV_DYN>>>(tmp, cnt, bufB, wh1, c1b,
                                                      nullptr, nullptr, sum1, sq1);
    mkscale<<<1, 64>>>(sum1, sq1, g1, b1, invV, sc1, sh1);

    // conv2: channels-last in with BN1+lrelu fused, channels-last out into tmp
    conv3d_mma<2><<<dim3(8, 32, BB), 256, CONV_DYN>>>(bufB, nullptr, tmp, wh2, c2b,
                                                      sc1, sh1, sum2, sq2);
    mkscale<<<1, 64>>>(sum2, sq2, g2, b2, invV, sc2, sh2);

    // point branch: fp16 tensor-core GEMM + fused stats
    pgemm_mma<<<dim3(NP / 128, BB), 256, PG_DYN>>>(fT, pw, pb, pT, psum, psq);
    mkscale<<<1, 64>>>(psum, psq, pg, pbeta, invP, scp, shp);

    // devoxelize (BN2+lrelu applied on gather) + point BN + add
    final_k<<<dim3(NP / 64, BB), 256>>>(tmp, pT, normc, sc2, sh2, scp, shp, out);

    // coords passthrough (second tuple output), if the harness expects it
    int main_sz = BB * CC * NP;
    int coord_sz = BB * 3 * NP;
    if (out_size >= main_sz + coord_sz)
        copy_kernel<<<coord_sz / 256, 256>>>(coords, out + main_sz, coord_sz);
}